// round 13
// baseline (speedup 1.0000x reference)
#include <cuda_runtime.h>
#include <cuda_fp16.h>
#include <math.h>
#include <stdint.h>

#define NTOK 8192
#define DDIM 1024
#define NEXP 32
#define HDIM 128
#define TOPK 4
#define CAP  8192
#define MT   64           // tokens per FFN tile (halved: occupancy)

// ---------------------------------------------------------------- helpers
__device__ __forceinline__ uint32_t smem_u32(const void* p) {
    uint32_t a;
    asm("{ .reg .u64 t; cvta.to.shared.u64 t, %1; cvt.u32.u64 %0, t; }" : "=r"(a) : "l"(p));
    return a;
}
__device__ __forceinline__ void ldsm_x4(uint32_t* r, uint32_t addr) {
    asm volatile("ldmatrix.sync.aligned.m8n8.x4.shared.b16 {%0,%1,%2,%3}, [%4];"
                 : "=r"(r[0]), "=r"(r[1]), "=r"(r[2]), "=r"(r[3]) : "r"(addr));
}
__device__ __forceinline__ void mma_f16(float* c, const uint32_t* a, const uint32_t* b) {
    asm volatile(
        "mma.sync.aligned.m16n8k16.row.col.f32.f16.f16.f32 "
        "{%0,%1,%2,%3},{%4,%5,%6,%7},{%8,%9},{%0,%1,%2,%3};"
        : "+f"(c[0]), "+f"(c[1]), "+f"(c[2]), "+f"(c[3])
        : "r"(a[0]), "r"(a[1]), "r"(a[2]), "r"(a[3]), "r"(b[0]), "r"(b[1]));
}
__device__ __forceinline__ uint32_t pack_f16(float a, float b) {
    __half2 h = __floats2half2_rn(a, b);
    return *(uint32_t*)&h;
}
__device__ __forceinline__ void cp16(uint32_t dst, const void* src, bool valid) {
    int sz = valid ? 16 : 0;
    asm volatile("cp.async.cg.shared.global [%0], [%1], 16, %2;"
                 :: "r"(dst), "l"(src), "r"(sz));
}
#define CP_COMMIT() asm volatile("cp.async.commit_group;" ::: "memory")
#define CP_WAIT1()  asm volatile("cp.async.wait_group 1;" ::: "memory")

// ---------------------------------------------------------------- scratch
__device__ int   g_count[NEXP];
__device__ int   g_eid [NTOK * TOPK];
__device__ float g_wt  [NTOK * TOPK];
__device__ int   g_dest [NEXP * CAP];
__device__ float g_gatew[NEXP * CAP];
__device__ __half g_ph [(size_t)NTOK * TOPK * DDIM];
__device__ __half g_xh [(size_t)NTOK * DDIM];
__device__ __half g_kth[(size_t)NEXP * HDIM * DDIM];
__device__ __half g_vth[(size_t)NEXP * DDIM * HDIM];

// ---------------- kernel 1: warp-per-token gate, float4 W loads ------------
__global__ __launch_bounds__(128) void gate_kernel(const float* __restrict__ x,
                                                   const float* __restrict__ W) {
    __shared__ float sg[4][NEXP];
    const int warp = threadIdx.x >> 5, lane = threadIdx.x & 31;
    const int t = blockIdx.x * 4 + warp;

    float4 xr[8];
    const float* xp = x + (size_t)t * DDIM;
    #pragma unroll
    for (int c = 0; c < 8; c++) {
        xr[c] = *(const float4*)(xp + c * 128 + lane * 4);
        uint2 h;
        h.x = pack_f16(xr[c].x, xr[c].y);
        h.y = pack_f16(xr[c].z, xr[c].w);
        *(uint2*)(g_xh + (size_t)t * DDIM + c * 128 + lane * 4) = h;
    }

    for (int e = 0; e < NEXP; e++) {
        const float4* wp = (const float4*)(W + (size_t)e * DDIM);
        float s = 0.f;
        #pragma unroll
        for (int c = 0; c < 8; c++) {
            float4 wv = wp[c * 32 + lane];
            s += xr[c].x * wv.x + xr[c].y * wv.y + xr[c].z * wv.z + xr[c].w * wv.w;
        }
        #pragma unroll
        for (int o = 16; o > 0; o >>= 1) s += __shfl_xor_sync(0xffffffffu, s, o);
        if (lane == 0) sg[warp][e] = s;
    }
    __syncwarp();

    if (lane == 0) {
        #pragma unroll
        for (int k = 0; k < TOPK; k++) {
            float best = -3.4e38f; int be = 0;
            for (int e = 0; e < NEXP; e++) {
                float v = sg[warp][e];
                if (v > best) { best = v; be = e; }
            }
            sg[warp][be] = -3.4e38f;
            g_eid[t * TOPK + k] = be;
            g_wt [t * TOPK + k] = 1.0f / (1.0f + expf(-best));
        }
    }
}

// ---------------- kernel 2: deterministic sorted routing -------------------
__global__ __launch_bounds__(1024) void route_kernel() {
    const int e = blockIdx.x;
    const int tid = threadIdx.x;
    const int lane = tid & 31, w = tid >> 5;
    __shared__ int warp_sums[32];
    __shared__ int s_base;
    if (tid == 0) s_base = 0;
    __syncthreads();

    for (int chunk = 0; chunk < NTOK; chunk += 1024) {
        int t = chunk + tid;
        int slot = -1; float wt = 0.f;
        #pragma unroll
        for (int k = 0; k < TOPK; k++) {
            if (g_eid[t * TOPK + k] == e) { slot = k; wt = g_wt[t * TOPK + k]; }
        }
        unsigned mask = __ballot_sync(0xffffffffu, slot >= 0);
        int wpre = __popc(mask & ((1u << lane) - 1));
        if (lane == 0) warp_sums[w] = __popc(mask);
        __syncthreads();
        int wbase = 0, tot = 0;
        #pragma unroll
        for (int i = 0; i < 32; i++) {
            int s = warp_sums[i];
            if (i < w) wbase += s;
            tot += s;
        }
        if (slot >= 0) {
            int pos = s_base + wbase + wpre;
            g_dest [e * CAP + pos] = t * TOPK + slot;
            g_gatew[e * CAP + pos] = wt;
        }
        __syncthreads();
        if (tid == 0) s_base += tot;
        __syncthreads();
    }
    if (tid == 0) g_count[e] = s_base;
}

// ---------------- kernel 3: K/V transpose to fp16 --------------------------
__global__ void convert_kernel(const float* __restrict__ keys,
                               const float* __restrict__ values) {
    __shared__ float tile[32][33];
    const int tid = threadIdx.x;
    const int tx = tid & 31, ty = tid >> 5;
    if (blockIdx.y == 0) {
        int bx = blockIdx.x, e = bx >> 7, rem = bx & 127;
        int d0 = (rem & 31) * 32, h0 = (rem >> 5) * 32;
        const float* src = keys + (size_t)e * DDIM * HDIM;
        #pragma unroll
        for (int i = 0; i < 4; i++)
            tile[ty + i * 8][tx] = src[(size_t)(d0 + ty + i * 8) * HDIM + h0 + tx];
        __syncthreads();
        #pragma unroll
        for (int i = 0; i < 4; i++)
            g_kth[((size_t)e * HDIM + h0 + ty + i * 8) * DDIM + d0 + tx] =
                __float2half(tile[tx][ty + i * 8]);
    } else {
        int bx = blockIdx.x, e = bx >> 7, rem = bx & 127;
        int h0 = (rem & 3) * 32, d0 = (rem >> 2) * 32;
        const float* src = values + (size_t)e * HDIM * DDIM;
        #pragma unroll
        for (int i = 0; i < 4; i++)
            tile[ty + i * 8][tx] = src[(size_t)(h0 + ty + i * 8) * DDIM + d0 + tx];
        __syncthreads();
        #pragma unroll
        for (int i = 0; i < 4; i++)
            g_vth[((size_t)e * DDIM + d0 + ty + i * 8) * HDIM + h0 + tx] =
                __float2half(tile[tx][ty + i * 8]);
    }
}

// ---------------- kernel 4: grouped FFN, MT=64, 3 CTAs/SM ------------------
// smem (56320 B/CTA):
//   0 s_dest[64] | 512 s_gate[64]
//   SM_ARENA = 1024:
//     GEMM1 stage s @ s*27648: A(64x144B) +0 | B(128x144B) +9216
//     GEMM2: H @ +0 (64x272B=17408) | B2 stage s @ +17408 + s*17408 (64x272B)
#define SM_DEST  0
#define SM_GATE  512
#define SM_ARENA 1024
#define G1_STAGE 27648
#define G1_B     9216
#define B2_OFF   17408
#define B2_STAGE 17408
#define SM_TOTAL (1024 + 55296)

__global__ __launch_bounds__(256, 3) void moe_ffn_mma() {
    extern __shared__ char smc[];
    const uint32_t smb = smem_u32(smc);
    const int e = blockIdx.y;
    const int cnt = g_count[e];
    const int start = blockIdx.x * MT;
    if (start >= cnt) return;
    const int ntok = min(MT, cnt - start);

    const int tid = threadIdx.x, lane = tid & 31, wid = tid >> 5;
    const int m0 = (wid & 3) * 16;        // 4 warps in M (16 rows each)
    const int n0 = (wid >> 2) * 64;       // 2 warps in N (GEMM1)
    const int n02 = (wid >> 2) * 32;      // GEMM2

    int*   s_dest = (int*)(smc + SM_DEST);
    float* s_gate = (float*)(smc + SM_GATE);
    if (tid < MT) {
        if (tid < ntok) {
            int idx = e * CAP + start + tid;
            s_dest[tid] = g_dest[idx];
            s_gate[tid] = g_gatew[idx];
        } else { s_dest[tid] = 0; s_gate[tid] = 0.f; }
    }
    __syncthreads();

    // staging geometry
    const int srowA = tid >> 2, shfA = tid & 3;   // A: 4 thr/row, 32B each
    const bool svalid = srowA < ntok;
    const size_t arowA = (size_t)(s_dest[srowA] >> 2) * DDIM;
    const int srowB = tid >> 1, shfB = tid & 1;   // B: 2 thr/row, 64B each
    const size_t browK = ((size_t)e * HDIM + srowB) * DDIM;
    const int srow2 = tid >> 2, shf2 = tid & 3;   // B2: 4 thr/row, 64B each

    const int rowo = (lane & 7) + ((lane >> 3) & 1) * 8;
    const int colx = (lane >> 4) * 8;

    auto stage1 = [&](int s, int kc) {
        uint32_t sbase = smb + SM_ARENA + s * G1_STAGE;
        // A: 64 rows x 64 halves (stride 144B); thread: 32B at shfA*32
        {
            uint32_t base = sbase + (uint32_t)srowA * 144 + shfA * 32;
            size_t ko = (size_t)kc * 64 + shfA * 16;
            cp16(base,      g_xh + arowA + ko,     svalid);
            cp16(base + 16, g_xh + arowA + ko + 8, svalid);
        }
        // B: 128 rows x 64 halves (stride 144B); thread: 64B at shfB*64
        {
            uint32_t base = sbase + G1_B + (uint32_t)srowB * 144 + shfB * 64;
            size_t ko = (size_t)kc * 64 + shfB * 32;
            #pragma unroll
            for (int j = 0; j < 4; j++)
                cp16(base + j * 16, g_kth + browK + ko + j * 8, true);
        }
    };
    auto stage2 = [&](int s, int nch) {
        size_t so = ((size_t)e * DDIM + nch * 64 + srow2) * HDIM + shf2 * 32;
        uint32_t base = smb + SM_ARENA + B2_OFF + s * B2_STAGE
                      + (uint32_t)srow2 * 272 + shf2 * 64;
        #pragma unroll
        for (int j = 0; j < 4; j++)
            cp16(base + j * 16, g_vth + so + j * 8, true);
    };

    float acc[8][4] = {};

    // ================= GEMM1: C1 = X @ keys^T ==============================
    stage1(0, 0);
    CP_COMMIT();
    for (int kc = 0; kc < DDIM / 64; kc++) {
        if (kc + 1 < DDIM / 64) stage1((kc + 1) & 1, kc + 1);
        CP_COMMIT();
        CP_WAIT1();
        __syncthreads();

        const uint32_t sb = smb + SM_ARENA + (kc & 1) * G1_STAGE;
        #pragma unroll
        for (int ks = 0; ks < 4; ks++) {
            const int kloc = ks * 16;
            uint32_t a[4], b[8][2];
            {
                uint32_t ao = (uint32_t)(m0 + rowo) * 144 + (kloc + colx) * 2;
                ldsm_x4(a, sb + ao);
            }
            #pragma unroll
            for (int p = 0; p < 4; p++) {
                uint32_t bo = (uint32_t)(n0 + p * 16 + rowo) * 144 + (kloc + colx) * 2;
                uint32_t bq[4];
                ldsm_x4(bq, sb + G1_B + bo);
                b[2 * p][0] = bq[0]; b[2 * p][1] = bq[2];
                b[2 * p + 1][0] = bq[1]; b[2 * p + 1][1] = bq[3];
            }
            #pragma unroll
            for (int nt2 = 0; nt2 < 8; nt2++)
                mma_f16(acc[nt2], a, b[nt2]);
        }
        __syncthreads();
    }

    stage2(0, 0);
    CP_COMMIT();

    // ================= epilogue1: H = relu(C1)*gate -> smem fp16 ===========
    {
        int rA = m0 + (lane >> 2);
        float gA = s_gate[rA], gB = s_gate[rA + 8];
        #pragma unroll
        for (int nt2 = 0; nt2 < 8; nt2++) {
            int col = n0 + nt2 * 8 + (lane & 3) * 2;
            float c0 = fmaxf(acc[nt2][0], 0.f) * gA;
            float c1 = fmaxf(acc[nt2][1], 0.f) * gA;
            float c2 = fmaxf(acc[nt2][2], 0.f) * gB;
            float c3 = fmaxf(acc[nt2][3], 0.f) * gB;
            *(uint32_t*)(smc + SM_ARENA + rA * 272 + col * 2)       = pack_f16(c0, c1);
            *(uint32_t*)(smc + SM_ARENA + (rA + 8) * 272 + col * 2) = pack_f16(c2, c3);
        }
    }

    // ================= GEMM2: out = H @ values^T, 16 chunks of 64 cols =====
    for (int nch = 0; nch < DDIM / 64; nch++) {
        if (nch + 1 < DDIM / 64) stage2((nch + 1) & 1, nch + 1);
        CP_COMMIT();
        CP_WAIT1();
        __syncthreads();

        const uint32_t hb = smb + SM_ARENA;
        const uint32_t b2 = smb + SM_ARENA + B2_OFF + (nch & 1) * B2_STAGE;
        float a2[4][4] = {};
        #pragma unroll
        for (int ks = 0; ks < 8; ks++) {
            const int kloc = ks * 16;
            uint32_t a[4], b[4][2];
            {
                uint32_t ao = (uint32_t)(m0 + rowo) * 272 + (kloc + colx) * 2;
                ldsm_x4(a, hb + ao);
            }
            #pragma unroll
            for (int p = 0; p < 2; p++) {
                uint32_t bo = (uint32_t)(n02 + p * 16 + rowo) * 272 + (kloc + colx) * 2;
                uint32_t bq[4];
                ldsm_x4(bq, b2 + bo);
                b[2 * p][0] = bq[0]; b[2 * p][1] = bq[2];
                b[2 * p + 1][0] = bq[1]; b[2 * p + 1][1] = bq[3];
            }
            #pragma unroll
            for (int nt2 = 0; nt2 < 4; nt2++)
                mma_f16(a2[nt2], a, b[nt2]);
        }

        // epilogue2: fp16 partial stores
        {
            int rA = m0 + (lane >> 2);
            #pragma unroll
            for (int nt2 = 0; nt2 < 4; nt2++) {
                int col = nch * 64 + n02 + nt2 * 8 + (lane & 3) * 2;
                if (rA < ntok)
                    *(uint32_t*)(g_ph + (size_t)s_dest[rA] * DDIM + col) =
                        pack_f16(a2[nt2][0], a2[nt2][1]);
                if (rA + 8 < ntok)
                    *(uint32_t*)(g_ph + (size_t)s_dest[rA + 8] * DDIM + col) =
                        pack_f16(a2[nt2][2], a2[nt2][3]);
            }
        }
        __syncthreads();
    }
}

// ---------------- kernel 5: gather 4 fp16 partial rows per token -----------
__global__ void gather_kernel(float* __restrict__ out) {
    int i = blockIdx.x * blockDim.x + threadIdx.x;
    int n = i >> 7, c = i & 127;
    const uint4* p = (const uint4*)g_ph;
    size_t base = (size_t)n * 4 * 128 + c;
    uint4 r0 = p[base], r1 = p[base + 128], r2 = p[base + 256], r3 = p[base + 384];
    float4 o0, o1;
    {
        float2 s0 = __half22float2(*(__half2*)&r0.x);
        float2 s1 = __half22float2(*(__half2*)&r1.x);
        float2 s2 = __half22float2(*(__half2*)&r2.x);
        float2 s3 = __half22float2(*(__half2*)&r3.x);
        o0.x = s0.x + s1.x + s2.x + s3.x; o0.y = s0.y + s1.y + s2.y + s3.y;
        s0 = __half22float2(*(__half2*)&r0.y); s1 = __half22float2(*(__half2*)&r1.y);
        s2 = __half22float2(*(__half2*)&r2.y); s3 = __half22float2(*(__half2*)&r3.y);
        o0.z = s0.x + s1.x + s2.x + s3.x; o0.w = s0.y + s1.y + s2.y + s3.y;
        s0 = __half22float2(*(__half2*)&r0.z); s1 = __half22float2(*(__half2*)&r1.z);
        s2 = __half22float2(*(__half2*)&r2.z); s3 = __half22float2(*(__half2*)&r3.z);
        o1.x = s0.x + s1.x + s2.x + s3.x; o1.y = s0.y + s1.y + s2.y + s3.y;
        s0 = __half22float2(*(__half2*)&r0.w); s1 = __half22float2(*(__half2*)&r1.w);
        s2 = __half22float2(*(__half2*)&r2.w); s3 = __half22float2(*(__half2*)&r3.w);
        o1.z = s0.x + s1.x + s2.x + s3.x; o1.w = s0.y + s1.y + s2.y + s3.y;
    }
    float* dst = out + (size_t)n * DDIM + c * 8;
    *(float4*)dst = o0;
    *(float4*)(dst + 4) = o1;
}

// ---------------- launch ----------------------------------------------------
extern "C" void kernel_launch(void* const* d_in, const int* in_sizes, int n_in,
                              void* d_out, int out_size) {
    const float* x      = (const float*)d_in[0];
    const float* W      = (const float*)d_in[1];
    const float* keys   = (const float*)d_in[2];
    const float* values = (const float*)d_in[3];
    float* out = (float*)d_out;

    cudaFuncSetAttribute(moe_ffn_mma, cudaFuncAttributeMaxDynamicSharedMemorySize, SM_TOTAL);

    gate_kernel<<<NTOK / 4, 128>>>(x, W);
    route_kernel<<<NEXP, 1024>>>();
    convert_kernel<<<dim3(4096, 2), 256>>>(keys, values);
    moe_ffn_mma<<<dim3(CAP / MT, NEXP), 256, SM_TOTAL>>>();
    gather_kernel<<<(NTOK * DDIM / 8) / 256, 256>>>(out);
}

// round 14
// speedup vs baseline: 1.1121x; 1.1121x over previous
#include <cuda_runtime.h>
#include <cuda_fp16.h>
#include <math.h>
#include <stdint.h>

#define NTOK 8192
#define DDIM 1024
#define NEXP 32
#define HDIM 128
#define TOPK 4
#define CAP  8192
#define MT   128          // tokens per FFN tile

// ---------------------------------------------------------------- helpers
__device__ __forceinline__ uint32_t smem_u32(const void* p) {
    uint32_t a;
    asm("{ .reg .u64 t; cvta.to.shared.u64 t, %1; cvt.u32.u64 %0, t; }" : "=r"(a) : "l"(p));
    return a;
}
__device__ __forceinline__ void ldsm_x4(uint32_t* r, uint32_t addr) {
    asm volatile("ldmatrix.sync.aligned.m8n8.x4.shared.b16 {%0,%1,%2,%3}, [%4];"
                 : "=r"(r[0]), "=r"(r[1]), "=r"(r[2]), "=r"(r[3]) : "r"(addr));
}
__device__ __forceinline__ void mma_f16(float* c, const uint32_t* a, const uint32_t* b) {
    asm volatile(
        "mma.sync.aligned.m16n8k16.row.col.f32.f16.f16.f32 "
        "{%0,%1,%2,%3},{%4,%5,%6,%7},{%8,%9},{%0,%1,%2,%3};"
        : "+f"(c[0]), "+f"(c[1]), "+f"(c[2]), "+f"(c[3])
        : "r"(a[0]), "r"(a[1]), "r"(a[2]), "r"(a[3]), "r"(b[0]), "r"(b[1]));
}
__device__ __forceinline__ uint32_t pack_f16(float a, float b) {
    __half2 h = __floats2half2_rn(a, b);
    return *(uint32_t*)&h;
}
__device__ __forceinline__ void cp16(uint32_t dst, const void* src, bool valid) {
    int sz = valid ? 16 : 0;
    asm volatile("cp.async.cg.shared.global [%0], [%1], 16, %2;"
                 :: "r"(dst), "l"(src), "r"(sz));
}
#define CP_COMMIT() asm volatile("cp.async.commit_group;" ::: "memory")
#define CP_WAIT1()  asm volatile("cp.async.wait_group 1;" ::: "memory")

// ---------------------------------------------------------------- scratch
__device__ int   g_count[NEXP];
__device__ int   g_eid [NTOK * TOPK];
__device__ float g_wt  [NTOK * TOPK];
__device__ int   g_dest [NEXP * CAP];
__device__ float g_gatew[NEXP * CAP];
__device__ __half g_ph [(size_t)NTOK * TOPK * DDIM];
__device__ __half g_xh [(size_t)NTOK * DDIM];
__device__ __half g_kth[(size_t)NEXP * HDIM * DDIM];
__device__ __half g_vth[(size_t)NEXP * DDIM * HDIM];

// ---------------- kernel 1 (merged): gate (warp/token) | K^T | V^T ---------
// blocks [0,1024): gate, 8 tokens each (8 warps). [1024,5120): keys^T.
// [5120,9216): values^T. All branches < 5 KB smem.
#define GATE_BLKS 1024
__global__ __launch_bounds__(256) void prep_kernel(
        const float* __restrict__ x,
        const float* __restrict__ W,
        const float* __restrict__ keys,
        const float* __restrict__ values) {
    __shared__ float shm[8][NEXP];       // gate scores OR aliased transpose tile
    __shared__ float tile[32][33];
    const int tid = threadIdx.x;
    const int bid = blockIdx.x;

    if (bid < GATE_BLKS) {
        const int warp = tid >> 5, lane = tid & 31;
        const int t = bid * 8 + warp;
        float4 xr[8];
        const float* xp = x + (size_t)t * DDIM;
        #pragma unroll
        for (int c = 0; c < 8; c++) {
            xr[c] = *(const float4*)(xp + c * 128 + lane * 4);
            uint2 h;
            h.x = pack_f16(xr[c].x, xr[c].y);
            h.y = pack_f16(xr[c].z, xr[c].w);
            *(uint2*)(g_xh + (size_t)t * DDIM + c * 128 + lane * 4) = h;
        }
        for (int e = 0; e < NEXP; e++) {
            const float4* wp = (const float4*)(W + (size_t)e * DDIM);
            float s = 0.f;
            #pragma unroll
            for (int c = 0; c < 8; c++) {
                float4 wv = wp[c * 32 + lane];
                s += xr[c].x * wv.x + xr[c].y * wv.y + xr[c].z * wv.z + xr[c].w * wv.w;
            }
            #pragma unroll
            for (int o = 16; o > 0; o >>= 1) s += __shfl_xor_sync(0xffffffffu, s, o);
            if (lane == 0) shm[warp][e] = s;
        }
        __syncwarp();
        if (lane == 0) {
            #pragma unroll
            for (int k = 0; k < TOPK; k++) {
                float best = -3.4e38f; int be = 0;
                for (int e = 0; e < NEXP; e++) {
                    float v = shm[warp][e];
                    if (v > best) { best = v; be = e; }
                }
                shm[warp][be] = -3.4e38f;
                g_eid[t * TOPK + k] = be;
                g_wt [t * TOPK + k] = 1.0f / (1.0f + expf(-best));
            }
        }
    } else if (bid < GATE_BLKS + 4096) {
        const int tx = tid & 31, ty = tid >> 5;
        int bx = bid - GATE_BLKS, e = bx >> 7, rem = bx & 127;
        int d0 = (rem & 31) * 32, h0 = (rem >> 5) * 32;
        const float* src = keys + (size_t)e * DDIM * HDIM;
        #pragma unroll
        for (int i = 0; i < 4; i++)
            tile[ty + i * 8][tx] = src[(size_t)(d0 + ty + i * 8) * HDIM + h0 + tx];
        __syncthreads();
        #pragma unroll
        for (int i = 0; i < 4; i++)
            g_kth[((size_t)e * HDIM + h0 + ty + i * 8) * DDIM + d0 + tx] =
                __float2half(tile[tx][ty + i * 8]);
    } else {
        const int tx = tid & 31, ty = tid >> 5;
        int bx = bid - GATE_BLKS - 4096, e = bx >> 7, rem = bx & 127;
        int h0 = (rem & 3) * 32, d0 = (rem >> 2) * 32;
        const float* src = values + (size_t)e * HDIM * DDIM;
        #pragma unroll
        for (int i = 0; i < 4; i++)
            tile[ty + i * 8][tx] = src[(size_t)(h0 + ty + i * 8) * DDIM + d0 + tx];
        __syncthreads();
        #pragma unroll
        for (int i = 0; i < 4; i++)
            g_vth[((size_t)e * DDIM + d0 + ty + i * 8) * HDIM + h0 + tx] =
                __float2half(tile[tx][ty + i * 8]);
    }
}

// ---------------- kernel 2: deterministic sorted routing -------------------
__global__ __launch_bounds__(1024) void route_kernel() {
    const int e = blockIdx.x;
    const int tid = threadIdx.x;
    const int lane = tid & 31, w = tid >> 5;
    __shared__ int warp_sums[32];
    __shared__ int s_base;
    if (tid == 0) s_base = 0;
    __syncthreads();

    for (int chunk = 0; chunk < NTOK; chunk += 1024) {
        int t = chunk + tid;
        int slot = -1; float wt = 0.f;
        #pragma unroll
        for (int k = 0; k < TOPK; k++) {
            if (g_eid[t * TOPK + k] == e) { slot = k; wt = g_wt[t * TOPK + k]; }
        }
        unsigned mask = __ballot_sync(0xffffffffu, slot >= 0);
        int wpre = __popc(mask & ((1u << lane) - 1));
        if (lane == 0) warp_sums[w] = __popc(mask);
        __syncthreads();
        int wbase = 0, tot = 0;
        #pragma unroll
        for (int i = 0; i < 32; i++) {
            int s = warp_sums[i];
            if (i < w) wbase += s;
            tot += s;
        }
        if (slot >= 0) {
            int pos = s_base + wbase + wpre;
            g_dest [e * CAP + pos] = t * TOPK + slot;
            g_gatew[e * CAP + pos] = wt;
        }
        __syncthreads();
        if (tid == 0) s_base += tot;
        __syncthreads();
    }
    if (tid == 0) g_count[e] = s_base;
}

// ---------------- kernel 3: grouped FFN, MT=128, 3-stage cp.async ring -----
// smem (111616 B/CTA -> 2 CTA/SM):
//   0 s_dest[128] | 512 s_gate[128]
//   SM_ARENA = 1024:
//     GEMM1 stage s (s<3) @ s*36864: A +0 | B +18432     (rows 144 B)
//     GEMM2: H @ +0 (34816, rows 272 B) | B2 stage s @ +36864 + s*17408
#define SM_DEST  0
#define SM_GATE  512
#define SM_ARENA 1024
#define G1_STAGE 36864
#define G1_B     18432
#define B2_OFF   36864
#define B2_STAGE 17408
#define SM_TOTAL (1024 + 3 * 36864)

__global__ __launch_bounds__(256, 2) void moe_ffn_mma() {
    extern __shared__ char smc[];
    const uint32_t smb = smem_u32(smc);
    const int e = blockIdx.y;
    const int cnt = g_count[e];
    const int start = blockIdx.x * MT;
    if (start >= cnt) return;
    const int ntok = min(MT, cnt - start);

    const int tid = threadIdx.x, lane = tid & 31, wid = tid >> 5;
    const int m0 = (wid & 3) * 32;
    const int n0 = (wid >> 2) * 64;
    const int n02 = (wid >> 2) * 32;

    int*   s_dest = (int*)(smc + SM_DEST);
    float* s_gate = (float*)(smc + SM_GATE);
    if (tid < MT) {
        if (tid < ntok) {
            int idx = e * CAP + start + tid;
            s_dest[tid] = g_dest[idx];
            s_gate[tid] = g_gatew[idx];
        } else { s_dest[tid] = 0; s_gate[tid] = 0.f; }
    }
    __syncthreads();

    const int srow = tid >> 1, shf = tid & 1;
    const bool svalid = srow < ntok;
    const size_t arowA = (size_t)(s_dest[srow] >> 2) * DDIM;
    const size_t browK = ((size_t)e * HDIM + srow) * DDIM;
    const int srow2 = tid >> 2, shf2 = tid & 3;

    const int rowo = (lane & 7) + ((lane >> 3) & 1) * 8;
    const int colx = (lane >> 4) * 8;

    auto stage1 = [&](int s, int kc) {
        uint32_t base = smb + SM_ARENA + s * G1_STAGE + (uint32_t)srow * 144 + shf * 64;
        size_t ko = (size_t)kc * 64 + shf * 32;
        #pragma unroll
        for (int j = 0; j < 4; j++) {
            cp16(base +        j * 16, g_xh  + arowA + ko + j * 8, svalid);
            cp16(base + G1_B + j * 16, g_kth + browK + ko + j * 8, true);
        }
    };
    auto stage2 = [&](int s, int nch) {
        size_t so = ((size_t)e * DDIM + nch * 64 + srow2) * HDIM + shf2 * 32;
        uint32_t base = smb + SM_ARENA + B2_OFF + s * B2_STAGE
                      + (uint32_t)srow2 * 272 + shf2 * 64;
        #pragma unroll
        for (int j = 0; j < 4; j++)
            cp16(base + j * 16, g_vth + so + j * 8, true);
    };

    float acc[2][8][4] = {};

    // ================= GEMM1: C1 = X @ keys^T (3-stage ring) ===============
    stage1(0, 0); CP_COMMIT();
    stage1(1, 1); CP_COMMIT();
    for (int kc = 0; kc < DDIM / 64; kc++) {
        CP_WAIT1();
        __syncthreads();                     // stage kc visible; frees stage kc%3 writers
        if (kc + 2 < DDIM / 64) stage1((kc + 2) % 3, kc + 2);
        CP_COMMIT();                         // empty commit on tail keeps counting exact

        const uint32_t sb = smb + SM_ARENA + (kc % 3) * G1_STAGE;
        #pragma unroll
        for (int ks = 0; ks < 4; ks++) {
            const int kloc = ks * 16;
            uint32_t a[2][4], b[8][2];
            #pragma unroll
            for (int mt2 = 0; mt2 < 2; mt2++) {
                uint32_t ao = (uint32_t)(m0 + mt2 * 16 + rowo) * 144 + (kloc + colx) * 2;
                ldsm_x4(a[mt2], sb + ao);
            }
            #pragma unroll
            for (int p = 0; p < 4; p++) {
                uint32_t bo = (uint32_t)(n0 + p * 16 + rowo) * 144 + (kloc + colx) * 2;
                uint32_t bq[4];
                ldsm_x4(bq, sb + G1_B + bo);
                b[2 * p][0] = bq[0]; b[2 * p][1] = bq[2];
                b[2 * p + 1][0] = bq[1]; b[2 * p + 1][1] = bq[3];
            }
            #pragma unroll
            for (int nt2 = 0; nt2 < 8; nt2++)
                #pragma unroll
                for (int mt2 = 0; mt2 < 2; mt2++)
                    mma_f16(acc[mt2][nt2], a[mt2], b[nt2]);
        }
        // no trailing barrier: next iteration's top barrier protects stage reuse
    }
    __syncthreads();                         // all warps done reading GEMM1 stages

    // prefetch first two B2 tiles (overlap epilogue1 register math)
    stage2(0, 0); CP_COMMIT();
    stage2(1, 1); CP_COMMIT();

    // ================= epilogue1: H = relu(C1)*gate -> smem fp16 ===========
    #pragma unroll
    for (int mt2 = 0; mt2 < 2; mt2++) {
        int rA = m0 + mt2 * 16 + (lane >> 2);
        float gA = s_gate[rA], gB = s_gate[rA + 8];
        #pragma unroll
        for (int nt2 = 0; nt2 < 8; nt2++) {
            int col = n0 + nt2 * 8 + (lane & 3) * 2;
            float c0 = fmaxf(acc[mt2][nt2][0], 0.f) * gA;
            float c1 = fmaxf(acc[mt2][nt2][1], 0.f) * gA;
            float c2 = fmaxf(acc[mt2][nt2][2], 0.f) * gB;
            float c3 = fmaxf(acc[mt2][nt2][3], 0.f) * gB;
            *(uint32_t*)(smc + SM_ARENA + rA * 272 + col * 2)       = pack_f16(c0, c1);
            *(uint32_t*)(smc + SM_ARENA + (rA + 8) * 272 + col * 2) = pack_f16(c2, c3);
        }
    }

    // ================= GEMM2: out = H @ values^T (3-stage ring) ============
    for (int nch = 0; nch < DDIM / 64; nch++) {
        CP_WAIT1();
        __syncthreads();                     // B2 stage nch + H writes visible
        if (nch + 2 < DDIM / 64) stage2((nch + 2) % 3, nch + 2);
        CP_COMMIT();

        const uint32_t hb = smb + SM_ARENA;
        const uint32_t b2 = smb + SM_ARENA + B2_OFF + (nch % 3) * B2_STAGE;
        float a2[2][4][4] = {};
        #pragma unroll
        for (int ks = 0; ks < 8; ks++) {
            const int kloc = ks * 16;
            uint32_t a[2][4], b[4][2];
            #pragma unroll
            for (int mt2 = 0; mt2 < 2; mt2++) {
                uint32_t ao = (uint32_t)(m0 + mt2 * 16 + rowo) * 272 + (kloc + colx) * 2;
                ldsm_x4(a[mt2], hb + ao);
            }
            #pragma unroll
            for (int p = 0; p < 2; p++) {
                uint32_t bo = (uint32_t)(n02 + p * 16 + rowo) * 272 + (kloc + colx) * 2;
                uint32_t bq[4];
                ldsm_x4(bq, b2 + bo);
                b[2 * p][0] = bq[0]; b[2 * p][1] = bq[2];
                b[2 * p + 1][0] = bq[1]; b[2 * p + 1][1] = bq[3];
            }
            #pragma unroll
            for (int nt2 = 0; nt2 < 4; nt2++)
                #pragma unroll
                for (int mt2 = 0; mt2 < 2; mt2++)
                    mma_f16(a2[mt2][nt2], a[mt2], b[nt2]);
        }

        // epilogue2: fp16 partial stores (register-only source; no smem hazard)
        #pragma unroll
        for (int mt2 = 0; mt2 < 2; mt2++) {
            int rA = m0 + mt2 * 16 + (lane >> 2);
            #pragma unroll
            for (int nt2 = 0; nt2 < 4; nt2++) {
                int col = nch * 64 + n02 + nt2 * 8 + (lane & 3) * 2;
                if (rA < ntok)
                    *(uint32_t*)(g_ph + (size_t)s_dest[rA] * DDIM + col) =
                        pack_f16(a2[mt2][nt2][0], a2[mt2][nt2][1]);
                if (rA + 8 < ntok)
                    *(uint32_t*)(g_ph + (size_t)s_dest[rA + 8] * DDIM + col) =
                        pack_f16(a2[mt2][nt2][2], a2[mt2][nt2][3]);
            }
        }
    }
}

// ---------------- kernel 4: gather 4 fp16 partial rows per token -----------
__global__ void gather_kernel(float* __restrict__ out) {
    int i = blockIdx.x * blockDim.x + threadIdx.x;
    int n = i >> 7, c = i & 127;
    const uint4* p = (const uint4*)g_ph;
    size_t base = (size_t)n * 4 * 128 + c;
    uint4 r0 = p[base], r1 = p[base + 128], r2 = p[base + 256], r3 = p[base + 384];
    float4 o0, o1;
    {
        float2 s0 = __half22float2(*(__half2*)&r0.x);
        float2 s1 = __half22float2(*(__half2*)&r1.x);
        float2 s2 = __half22float2(*(__half2*)&r2.x);
        float2 s3 = __half22float2(*(__half2*)&r3.x);
        o0.x = s0.x + s1.x + s2.x + s3.x; o0.y = s0.y + s1.y + s2.y + s3.y;
        s0 = __half22float2(*(__half2*)&r0.y); s1 = __half22float2(*(__half2*)&r1.y);
        s2 = __half22float2(*(__half2*)&r2.y); s3 = __half22float2(*(__half2*)&r3.y);
        o0.z = s0.x + s1.x + s2.x + s3.x; o0.w = s0.y + s1.y + s2.y + s3.y;
        s0 = __half22float2(*(__half2*)&r0.z); s1 = __half22float2(*(__half2*)&r1.z);
        s2 = __half22float2(*(__half2*)&r2.z); s3 = __half22float2(*(__half2*)&r3.z);
        o1.x = s0.x + s1.x + s2.x + s3.x; o1.y = s0.y + s1.y + s2.y + s3.y;
        s0 = __half22float2(*(__half2*)&r0.w); s1 = __half22float2(*(__half2*)&r1.w);
        s2 = __half22float2(*(__half2*)&r2.w); s3 = __half22float2(*(__half2*)&r3.w);
        o1.z = s0.x + s1.x + s2.x + s3.x; o1.w = s0.y + s1.y + s2.y + s3.y;
    }
    float* dst = out + (size_t)n * DDIM + c * 8;
    *(float4*)dst = o0;
    *(float4*)(dst + 4) = o1;
}

// ---------------- launch ----------------------------------------------------
extern "C" void kernel_launch(void* const* d_in, const int* in_sizes, int n_in,
                              void* d_out, int out_size) {
    const float* x      = (const float*)d_in[0];
    const float* W      = (const float*)d_in[1];
    const float* keys   = (const float*)d_in[2];
    const float* values = (const float*)d_in[3];
    float* out = (float*)d_out;

    cudaFuncSetAttribute(moe_ffn_mma, cudaFuncAttributeMaxDynamicSharedMemorySize, SM_TOTAL);

    prep_kernel<<<GATE_BLKS + 8192, 256>>>(x, W, keys, values);
    route_kernel<<<NEXP, 1024>>>();
    moe_ffn_mma<<<dim3(CAP / MT, NEXP), 256, SM_TOTAL>>>();
    gather_kernel<<<(NTOK * DDIM / 8) / 256, 256>>>(out);
}